// round 11
// baseline (speedup 1.0000x reference)
#include <cuda_runtime.h>
#include <cstdint>

#define NN 50000
#define EE 800000
#define RR 8
#define HD 128
#define NG 2                      // graphs
#define NT ((NN + 127) / 128)     // 391 dst tiles
#define NB (NG * NT * RR)         // 6256 buckets

#define SA 132                    // S row stride (words): A-frag conflict-free
#define SBW 136                   // Wb row stride (words): B-frag conflict-free
#define EBCAP 768                 // per-bucket edge capacity (avg 256)

// smem word offsets
#define OFF_WB   (128 * SA)                  // 16896
#define OFF_EB   (OFF_WB + 32 * SBW)         // 21248
#define OFF_EB2  (OFF_EB + EBCAP * 2)        // 22784
#define OFF_CNT  (OFF_EB2 + EBCAP * 2)       // 24320
#define OFF_OFFA (OFF_CNT + 128)             // 24448  (129 entries)
#define OFF_CUR  (OFF_OFFA + 129)            // 24577
#define SMEM_WORDS (OFF_CUR + 128)           // 24705
#define FUSED_SMEM (SMEM_WORDS * 4)          // 98820 B -> 2 CTAs/SM

// ---------------- scratch (device globals; no allocation allowed) ----------
__device__ float    g_denom[NG * NN];
__device__ float    g_wq[NG * RR * HD];
__device__ float    g_wk[NG * RR * HD];
__device__ float    g_qi[NG * NN * RR];
__device__ float    g_kj[NG * NN * RR];
__device__ uint32_t g_cnt[NB];
__device__ uint32_t g_off[NB + 1];
__device__ uint32_t g_cur[NB];
__device__ uint2    g_es[(size_t)NG * EE];  // .x = src | (dst&127)<<16, .y = ex

__device__ __forceinline__ uint32_t f2tf32(float f) {
    uint32_t u;
    asm("cvt.rna.tf32.f32 %0, %1;" : "=r"(u) : "f"(f));
    return u;
}

// ---------------- zero denom + bucket counts --------------------------------
__global__ void prep_kernel() {
    int i = blockIdx.x * blockDim.x + threadIdx.x;
    int stride = gridDim.x * blockDim.x;
    for (int j = i; j < NG * NN; j += stride) g_denom[j] = 0.f;
    for (int j = i; j < NB; j += stride) g_cnt[j] = 0u;
}

// ---------------- Wq[r] = W_r @ q, Wk[r] = W_r @ k --------------------------
__global__ void wqwk_kernel(const float* __restrict__ W1, const float* __restrict__ q1,
                            const float* __restrict__ k1,
                            const float* __restrict__ W2, const float* __restrict__ q2,
                            const float* __restrict__ k2) {
    int graph = blockIdx.y;
    const float* W = graph ? W2 : W1;
    const float* q = graph ? q2 : q1;
    const float* k = graph ? k2 : k1;
    int w = (blockIdx.x * blockDim.x + threadIdx.x) >> 5;
    int lane = threadIdx.x & 31;
    if (w >= RR * HD) return;
    const float* row = W + (size_t)w * HD;
    float sq = 0.f, sk = 0.f;
#pragma unroll
    for (int j = lane; j < HD; j += 32) {
        float wv = row[j];
        sq += wv * q[j];
        sk += wv * k[j];
    }
#pragma unroll
    for (int o = 16; o; o >>= 1) {
        sq += __shfl_xor_sync(0xffffffffu, sq, o);
        sk += __shfl_xor_sync(0xffffffffu, sk, o);
    }
    if (lane == 0) {
        g_wq[graph * RR * HD + w] = sq;
        g_wk[graph * RR * HD + w] = sk;
    }
}

// ---------------- per-node logit tables: qi[n][r], kj[n][r] -----------------
__global__ void table_kernel(const float* __restrict__ x1,
                             const float* __restrict__ x2) {
    int graph = blockIdx.y;
    const float* x = graph ? x2 : x1;
    int n = (blockIdx.x * blockDim.x + threadIdx.x) >> 5;
    if (n >= NN) return;
    int lane = threadIdx.x & 31;
    float4 xv = ((const float4*)x)[(size_t)n * 32 + lane];
    const float4* wq4 = (const float4*)(g_wq + graph * RR * HD);
    const float4* wk4 = (const float4*)(g_wk + graph * RR * HD);
#pragma unroll
    for (int r = 0; r < RR; r++) {
        float4 wq = wq4[r * 32 + lane];
        float4 wk = wk4[r * 32 + lane];
        float sq = xv.x * wq.x + xv.y * wq.y + xv.z * wq.z + xv.w * wq.w;
        float sk = xv.x * wk.x + xv.y * wk.y + xv.z * wk.z + xv.w * wk.w;
#pragma unroll
        for (int o = 16; o; o >>= 1) {
            sq += __shfl_xor_sync(0xffffffffu, sq, o);
            sk += __shfl_xor_sync(0xffffffffu, sk, o);
        }
        if (lane == 0) {
            g_qi[(graph * NN + n) * RR + r] = sq;
            g_kj[(graph * NN + n) * RR + r] = sk;
        }
    }
}

// ---------------- histogram over (dst-tile, relation) buckets ---------------
__global__ void hist_kernel(const int* __restrict__ ei1, const int* __restrict__ et1,
                            const int* __restrict__ ei2, const int* __restrict__ et2) {
    __shared__ uint32_t h[NT * RR];
    int graph = blockIdx.y;
    const int* ei = graph ? ei2 : ei1;
    const int* et = graph ? et2 : et1;
    for (int i = threadIdx.x; i < NT * RR; i += 256) h[i] = 0u;
    __syncthreads();
    int base = blockIdx.x * 4096;
#pragma unroll
    for (int i = 0; i < 16; i++) {
        int e = base + threadIdx.x + i * 256;
        if (e < EE) {
            int dst = __ldg(ei + EE + e);
            int r = __ldg(et + e);
            atomicAdd(&h[(dst >> 7) * RR + r], 1u);
        }
    }
    __syncthreads();
    uint32_t* cnt = g_cnt + graph * NT * RR;
    for (int i = threadIdx.x; i < NT * RR; i += 256)
        if (h[i]) atomicAdd(&cnt[i], h[i]);
}

// ---------------- exclusive scan over NB buckets (single block) -------------
__global__ void scan_kernel() {
    __shared__ uint32_t part[256];
    const int per = (NB + 255) / 256;   // 25
    int t = threadIdx.x;
    uint32_t loc[per];
    uint32_t s = 0;
#pragma unroll
    for (int i = 0; i < per; i++) {
        int idx = t * per + i;
        uint32_t v = (idx < NB) ? g_cnt[idx] : 0u;
        loc[i] = s;
        s += v;
    }
    part[t] = s;
    __syncthreads();
    for (int o = 1; o < 256; o <<= 1) {
        uint32_t v = (t >= o) ? part[t - o] : 0u;
        __syncthreads();
        part[t] += v;
        __syncthreads();
    }
    uint32_t base = t ? part[t - 1] : 0u;
#pragma unroll
    for (int i = 0; i < per; i++) {
        int idx = t * per + i;
        if (idx < NB) {
            uint32_t off = base + loc[i];
            g_off[idx] = off;
            g_cur[idx] = off;
        }
    }
    if (t == 255) g_off[NB] = part[255];
}

// ---------------- reorder edges into dst buckets + denom + ex ---------------
__global__ void reorder_kernel(const int* __restrict__ ei1, const int* __restrict__ et1,
                               const int* __restrict__ ei2, const int* __restrict__ et2) {
    int graph = blockIdx.y;
    const int* ei = graph ? ei2 : ei1;
    const int* et = graph ? et2 : et1;
    int e = blockIdx.x * 256 + threadIdx.x;
    if (e >= EE) return;
    int src = __ldg(ei + e);
    int dst = __ldg(ei + EE + e);
    int r = __ldg(et + e);
    float al = g_qi[(graph * NN + dst) * RR + r] + g_kj[(graph * NN + src) * RR + r];
    al = al > 0.f ? al : 0.2f * al;          // leaky_relu
    float ex = __expf(al);                   // alpha ~ O(1): no max-shift
    atomicAdd(&g_denom[graph * NN + dst], ex);
    uint32_t key = (graph * NT + (dst >> 7)) * RR + r;
    uint32_t p = atomicAdd(&g_cur[key], 1u);
    g_es[p] = make_uint2((uint32_t)src | ((uint32_t)(dst & 127) << 16),
                         __float_as_uint(ex));
}

// ---------------- fused: sort + pipelined gather + GEMM + epilogue ----------
// CTA = (dst-tile, graph). Per r: counting-sort bucket edges by dst row;
// warp w owns rows w, w+8, ...; flat software-pipelined walk over its
// row-sorted edges (prefetch next x[src] before consuming current -> MLP),
// register accumulate, one tf32 store per row. Then MMA S @ W_r into acc.
__global__ __launch_bounds__(256, 2)
void fused_agg(const float* __restrict__ x1, const float* __restrict__ x2,
               const float* __restrict__ W1, const float* __restrict__ W2,
               const float* __restrict__ b1, const float* __restrict__ b2,
               float* __restrict__ out) {
    extern __shared__ uint32_t sm[];
    float*    S   = (float*)sm;             // [128][SA]; tf32 bits where gathered
    uint32_t* Su  = sm;
    uint32_t* Wb  = sm + OFF_WB;            // [32][SBW]
    uint2*    EB  = (uint2*)(sm + OFF_EB);  // raw bucket edges
    uint2*    EB2 = (uint2*)(sm + OFF_EB2); // row-sorted edges
    uint32_t* cnt = sm + OFF_CNT;           // [128]
    uint32_t* off = sm + OFF_OFFA;          // [129]
    uint32_t* cur = sm + OFF_CUR;           // [128]

    int graph = blockIdx.y;
    int tile = blockIdx.x;
    const float* x = graph ? x2 : x1;
    const float* W = graph ? W2 : W1;
    const float* bias = graph ? b2 : b1;
    int m0 = tile * 128;
    int tid = threadIdx.x, wid = tid >> 5, lane = tid & 31;
    int warpM = wid >> 1, warpN = wid & 1;
    int g = lane >> 2, t = lane & 3;
    const float4* x4 = (const float4*)x;

    float acc[2][8][4];
#pragma unroll
    for (int mt = 0; mt < 2; mt++)
#pragma unroll
        for (int nt = 0; nt < 8; nt++)
#pragma unroll
            for (int c = 0; c < 4; c++) acc[mt][nt][c] = 0.f;

    for (int r = 0; r < RR; r++) {
        uint32_t key = (graph * NT + tile) * RR + r;
        uint32_t beg = g_off[key];
        int n = (int)(g_off[key + 1] - beg);
        if (n > EBCAP) n = EBCAP;   // statistically unreachable guard

        // zero S (tf32 0 == f32 0)
        float4 z = make_float4(0.f, 0.f, 0.f, 0.f);
        for (int i = tid; i < 128 * SA / 4; i += 256) ((float4*)S)[i] = z;
        // load bucket edges + zero bins
        for (int i = tid; i < n; i += 256) EB[i] = g_es[beg + i];
        if (tid < 128) cnt[tid] = 0u;
        __syncthreads();

        // histogram by dst row
        for (int i = tid; i < n; i += 256)
            atomicAdd(&cnt[(EB[i].x >> 16) & 0x7f], 1u);
        __syncthreads();

        // warp 0: exclusive scan of 128 bins (4 per lane)
        if (wid == 0) {
            uint32_t v0 = cnt[lane * 4], v1 = cnt[lane * 4 + 1];
            uint32_t v2 = cnt[lane * 4 + 2], v3 = cnt[lane * 4 + 3];
            uint32_t sum = v0 + v1 + v2 + v3;
            uint32_t incl = sum;
#pragma unroll
            for (int o = 1; o < 32; o <<= 1) {
                uint32_t tv = __shfl_up_sync(0xffffffffu, incl, o);
                if (lane >= o) incl += tv;
            }
            uint32_t run = incl - sum;
            off[lane * 4] = run;     cur[lane * 4] = run;     run += v0;
            off[lane * 4 + 1] = run; cur[lane * 4 + 1] = run; run += v1;
            off[lane * 4 + 2] = run; cur[lane * 4 + 2] = run; run += v2;
            off[lane * 4 + 3] = run; cur[lane * 4 + 3] = run; run += v3;
            if (lane == 31) off[128] = run;
        }
        __syncthreads();

        // scatter edges into row-sorted order
        for (int i = tid; i < n; i += 256) {
            uint2 e = EB[i];
            uint32_t p = atomicAdd(&cur[(e.x >> 16) & 0x7f], 1u);
            EB2[p] = e;
        }
        __syncthreads();

        // ---- pipelined gather: warp wid owns rows wid, wid+8, ... ----
        {
            int lc = wid;
            uint32_t j = off[lc], jend = off[lc + 1];
            while (j >= jend && lc <= 119) { lc += 8; j = off[lc]; jend = off[lc + 1]; }
            bool valid = (j < jend);
            uint2 e0 = make_uint2(0u, 0u);
            float4 xv0 = z;
            if (valid) {
                e0 = EB2[j];
                xv0 = __ldg(&x4[(size_t)(e0.x & 0xffff) * 32 + lane]);
            }
            float4 s = z;
            while (valid) {
                // advance to next owned edge (may cross rows) + prefetch
                int lcN = lc;
                uint32_t jN = j + 1, jendN = jend;
                while (jN >= jendN && lcN <= 119) {
                    lcN += 8; jN = off[lcN]; jendN = off[lcN + 1];
                }
                bool validN = (jN < jendN);
                uint2 e1 = make_uint2(0u, 0u);
                float4 xv1 = z;
                if (validN) {
                    e1 = EB2[jN];
                    xv1 = __ldg(&x4[(size_t)(e1.x & 0xffff) * 32 + lane]);
                }
                float ex = __uint_as_float(e0.y);
                s.x += ex * xv0.x; s.y += ex * xv0.y;
                s.z += ex * xv0.z; s.w += ex * xv0.w;
                if (!validN || lcN != lc) {
                    // row finished: single tf32 store
                    uint4 u = make_uint4(f2tf32(s.x), f2tf32(s.y),
                                         f2tf32(s.z), f2tf32(s.w));
                    *(uint4*)&Su[lc * SA + lane * 4] = u;
                    s = z;
                }
                lc = lcN; j = jN; jend = jendN;
                e0 = e1; xv0 = xv1; valid = validN;
            }
        }
        __syncthreads();

        // MMA: acc += S @ W_r
        const float* Wr = W + (size_t)r * HD * HD;
        for (int kc = 0; kc < HD; kc += 32) {
            for (int i = tid; i < 32 * 32; i += 256) {
                int row = i >> 5, c4 = i & 31;
                float4 v = ((const float4*)Wr)[(size_t)(kc + row) * 32 + c4];
                uint4 u = make_uint4(f2tf32(v.x), f2tf32(v.y), f2tf32(v.z), f2tf32(v.w));
                *(uint4*)&Wb[row * SBW + c4 * 4] = u;
            }
            __syncthreads();
#pragma unroll
            for (int kk = 0; kk < 32; kk += 8) {
                int kbase = kc + kk;
                uint32_t a[2][4];
#pragma unroll
                for (int mt = 0; mt < 2; mt++) {
                    int rb = warpM * 32 + mt * 16 + g;
                    a[mt][0] = Su[rb * SA + kbase + t];
                    a[mt][1] = Su[(rb + 8) * SA + kbase + t];
                    a[mt][2] = Su[rb * SA + kbase + t + 4];
                    a[mt][3] = Su[(rb + 8) * SA + kbase + t + 4];
                }
#pragma unroll
                for (int nt = 0; nt < 8; nt++) {
                    int col = warpN * 64 + nt * 8 + g;
                    uint32_t b0 = Wb[(kk + t) * SBW + col];
                    uint32_t b1v = Wb[(kk + t + 4) * SBW + col];
#pragma unroll
                    for (int mt = 0; mt < 2; mt++) {
                        asm volatile(
                            "mma.sync.aligned.m16n8k8.row.col.f32.tf32.tf32.f32 "
                            "{%0,%1,%2,%3}, {%4,%5,%6,%7}, {%8,%9}, {%0,%1,%2,%3};"
                            : "+f"(acc[mt][nt][0]), "+f"(acc[mt][nt][1]),
                              "+f"(acc[mt][nt][2]), "+f"(acc[mt][nt][3])
                            : "r"(a[mt][0]), "r"(a[mt][1]), "r"(a[mt][2]), "r"(a[mt][3]),
                              "r"(b0), "r"(b1v));
                    }
                }
            }
            __syncthreads();
        }
    }

    // epilogue: out = relu(acc / denom + bias)
#pragma unroll
    for (int mt = 0; mt < 2; mt++) {
        int row0 = m0 + warpM * 32 + mt * 16 + g;
        float inv0 = 0.f, inv8 = 0.f;
        if (row0 < NN)     inv0 = 1.0f / (g_denom[graph * NN + row0] + 1e-16f);
        if (row0 + 8 < NN) inv8 = 1.0f / (g_denom[graph * NN + row0 + 8] + 1e-16f);
#pragma unroll
        for (int nt = 0; nt < 8; nt++) {
            int col = warpN * 64 + nt * 8 + t * 2;
            float bb0 = __ldg(bias + col), bb1 = __ldg(bias + col + 1);
            if (row0 < NN) {
                float2 v;
                v.x = fmaxf(acc[mt][nt][0] * inv0 + bb0, 0.f);
                v.y = fmaxf(acc[mt][nt][1] * inv0 + bb1, 0.f);
                *(float2*)&out[((size_t)graph * NN + row0) * HD + col] = v;
            }
            if (row0 + 8 < NN) {
                float2 v;
                v.x = fmaxf(acc[mt][nt][2] * inv8 + bb0, 0.f);
                v.y = fmaxf(acc[mt][nt][3] * inv8 + bb1, 0.f);
                *(float2*)&out[((size_t)graph * NN + row0 + 8) * HD + col] = v;
            }
        }
    }
}

// ---------------- driver ----------------------------------------------------
extern "C" void kernel_launch(void* const* d_in, const int* in_sizes, int n_in,
                              void* d_out, int out_size) {
    const float* x1  = (const float*)d_in[0];
    const int*   ei1 = (const int*)d_in[1];
    const int*   et1 = (const int*)d_in[2];
    const float* x2  = (const float*)d_in[3];
    const int*   ei2 = (const int*)d_in[4];
    const int*   et2 = (const int*)d_in[5];
    const float* W1  = (const float*)d_in[6];
    const float* q1  = (const float*)d_in[7];
    const float* k1  = (const float*)d_in[8];
    const float* b1  = (const float*)d_in[9];
    const float* W2  = (const float*)d_in[10];
    const float* q2  = (const float*)d_in[11];
    const float* k2  = (const float*)d_in[12];
    const float* b2  = (const float*)d_in[13];
    float* out = (float*)d_out;

    cudaFuncSetAttribute(fused_agg,
                         cudaFuncAttributeMaxDynamicSharedMemorySize, FUSED_SMEM);

    prep_kernel<<<256, 256>>>();
    wqwk_kernel<<<dim3((RR * HD) / 8, NG), 256>>>(W1, q1, k1, W2, q2, k2);
    table_kernel<<<dim3((NN + 7) / 8, NG), 256>>>(x1, x2);
    hist_kernel<<<dim3((EE + 4095) / 4096, NG), 256>>>(ei1, et1, ei2, et2);
    scan_kernel<<<1, 256>>>();
    reorder_kernel<<<dim3((EE + 255) / 256, NG), 256>>>(ei1, et1, ei2, et2);
    fused_agg<<<dim3(NT, NG), 256, FUSED_SMEM>>>(x1, x2, W1, W2, b1, b2, out);
}

// round 14
// speedup vs baseline: 1.2012x; 1.2012x over previous
#include <cuda_runtime.h>
#include <cstdint>

#define NN 50000
#define EE 800000
#define RR 8
#define HD 128
#define NG 2            // graphs

#define GM 128
#define SA 132          // A tile row stride (words): conflict-free frags
#define SBW 136         // B chunk row stride (words): conflict-free frags
#define MBLK ((NN + GM - 1) / GM)
#define GEMM_SMEM ((GM * SA + 32 * SBW) * 4)   // 84992 -> 2 CTAs/SM

// ---------------- scratch (device globals; no allocation allowed) ----------
__device__ uint4 g_xt[(size_t)NG * RR * NN * 16];  // 204.8 MB xt fp16 [g][r][n][128]
__device__ float g_acc[(size_t)NG * NN * HD];      // 51.2 MB unnormalized agg
__device__ float g_denom[NG * NN];
__device__ float g_wq[NG * RR * HD];
__device__ float g_wk[NG * RR * HD];
__device__ float g_qi[NG * NN * RR];
__device__ float g_kj[NG * NN * RR];

__device__ __forceinline__ uint32_t f2tf32(float f) {
    uint32_t u;
    asm("cvt.rna.tf32.f32 %0, %1;" : "=r"(u) : "f"(f));
    return u;
}
// pack two f32 -> f16x2 (lo in low half, hi in high half)
__device__ __forceinline__ uint32_t pack_f16x2(float lo, float hi) {
    uint32_t r;
    asm("cvt.rn.f16x2.f32 %0, %1, %2;" : "=r"(r) : "f"(hi), "f"(lo));
    return r;
}
// unpack f16x2 -> two f32
__device__ __forceinline__ float2 unpack_f16x2(uint32_t u) {
    float lo, hi;
    asm("{ .reg .b16 l, h;\n\t"
        "  mov.b32 {l, h}, %2;\n\t"
        "  cvt.f32.f16 %0, l;\n\t"
        "  cvt.f32.f16 %1, h; }"
        : "=f"(lo), "=f"(hi) : "r"(u));
    return make_float2(lo, hi);
}

// ---------------- zero acc + denom -----------------------------------------
__global__ void prep_kernel() {
    int i = blockIdx.x * blockDim.x + threadIdx.x;
    int stride = gridDim.x * blockDim.x;
    float4 z = make_float4(0.f, 0.f, 0.f, 0.f);
    float4* a4 = (float4*)g_acc;
    const int na4 = NG * NN * HD / 4;
    for (int j = i; j < na4; j += stride) a4[j] = z;
    for (int j = i; j < NG * NN; j += stride) g_denom[j] = 0.f;
}

// ---------------- Wq[r] = W_r @ q, Wk[r] = W_r @ k --------------------------
__global__ void wqwk_kernel(const float* __restrict__ W1, const float* __restrict__ q1,
                            const float* __restrict__ k1,
                            const float* __restrict__ W2, const float* __restrict__ q2,
                            const float* __restrict__ k2) {
    int graph = blockIdx.y;
    const float* W = graph ? W2 : W1;
    const float* q = graph ? q2 : q1;
    const float* k = graph ? k2 : k1;
    int w = (blockIdx.x * blockDim.x + threadIdx.x) >> 5;
    int lane = threadIdx.x & 31;
    if (w >= RR * HD) return;
    const float* row = W + (size_t)w * HD;
    float sq = 0.f, sk = 0.f;
#pragma unroll
    for (int j = lane; j < HD; j += 32) {
        float wv = row[j];
        sq += wv * q[j];
        sk += wv * k[j];
    }
#pragma unroll
    for (int o = 16; o; o >>= 1) {
        sq += __shfl_xor_sync(0xffffffffu, sq, o);
        sk += __shfl_xor_sync(0xffffffffu, sk, o);
    }
    if (lane == 0) {
        g_wq[graph * RR * HD + w] = sq;
        g_wk[graph * RR * HD + w] = sk;
    }
}

// ---------------- per-node logit tables: qi[n][r], kj[n][r] -----------------
__global__ void table_kernel(const float* __restrict__ x1,
                             const float* __restrict__ x2) {
    int graph = blockIdx.y;
    const float* x = graph ? x2 : x1;
    int n = (blockIdx.x * blockDim.x + threadIdx.x) >> 5;
    if (n >= NN) return;
    int lane = threadIdx.x & 31;
    float4 xv = ((const float4*)x)[(size_t)n * 32 + lane];
    const float4* wq4 = (const float4*)(g_wq + graph * RR * HD);
    const float4* wk4 = (const float4*)(g_wk + graph * RR * HD);
#pragma unroll
    for (int r = 0; r < RR; r++) {
        float4 wq = wq4[r * 32 + lane];
        float4 wk = wk4[r * 32 + lane];
        float sq = xv.x * wq.x + xv.y * wq.y + xv.z * wq.z + xv.w * wq.w;
        float sk = xv.x * wk.x + xv.y * wk.y + xv.z * wk.z + xv.w * wk.w;
#pragma unroll
        for (int o = 16; o; o >>= 1) {
            sq += __shfl_xor_sync(0xffffffffu, sq, o);
            sk += __shfl_xor_sync(0xffffffffu, sk, o);
        }
        if (lane == 0) {
            g_qi[(graph * NN + n) * RR + r] = sq;
            g_kj[(graph * NN + n) * RR + r] = sk;
        }
    }
}

// ---------------- xt[g][r] = x @ W_r  (tf32 mma.sync, fp16 store) -----------
// A tile resident in smem (loaded ONCE), loop over r with B streamed in
// 32-row chunks. 85KB smem -> 2 CTAs/SM. No min-blocks bound (R4 lesson).
__global__ __launch_bounds__(256)
void xt_gemm(const float* __restrict__ x1, const float* __restrict__ x2,
             const float* __restrict__ W1, const float* __restrict__ W2) {
    extern __shared__ uint32_t sm[];
    uint32_t* As = sm;              // [128][SA]  x tile (tf32 bits)
    uint32_t* Bs = sm + GM * SA;    // [32][SBW]  W chunk (tf32 bits)
    int graph = blockIdx.y;
    const float* x = graph ? x2 : x1;
    const float* W = graph ? W2 : W1;
    int m0 = blockIdx.x * GM;
    int tid = threadIdx.x;
    int wid = tid >> 5, lane = tid & 31;
    int warpM = wid >> 1;    // 0..3 -> 32-row slab
    int warpN = wid & 1;     // 0..1 -> 64-col slab
    int g = lane >> 2, t = lane & 3;

    // load A tile once, convert to tf32
    for (int idx = tid; idx < GM * 32; idx += 256) {
        int row = idx >> 5, c4 = idx & 31;
        int gm = m0 + row;
        float4 v = make_float4(0.f, 0.f, 0.f, 0.f);
        if (gm < NN) v = ((const float4*)x)[(size_t)gm * 32 + c4];
        uint4 u = make_uint4(f2tf32(v.x), f2tf32(v.y), f2tf32(v.z), f2tf32(v.w));
        *(uint4*)&As[row * SA + c4 * 4] = u;
    }

    for (int r = 0; r < RR; r++) {
        const float* Wr = W + (size_t)r * HD * HD;
        float acc[2][8][4];
#pragma unroll
        for (int mt = 0; mt < 2; mt++)
#pragma unroll
            for (int nt = 0; nt < 8; nt++)
#pragma unroll
                for (int c = 0; c < 4; c++) acc[mt][nt][c] = 0.f;

        for (int kc = 0; kc < HD; kc += 32) {
            __syncthreads();
#pragma unroll
            for (int i = 0; i < 4; i++) {
                int idx = tid + i * 256;
                int row = idx >> 5, c4 = idx & 31;
                float4 v = ((const float4*)Wr)[(size_t)(kc + row) * 32 + c4];
                uint4 u = make_uint4(f2tf32(v.x), f2tf32(v.y), f2tf32(v.z), f2tf32(v.w));
                *(uint4*)&Bs[row * SBW + c4 * 4] = u;
            }
            __syncthreads();
#pragma unroll
            for (int kk = 0; kk < 32; kk += 8) {
                int kbase = kc + kk;
                uint32_t a[2][4];
#pragma unroll
                for (int mt = 0; mt < 2; mt++) {
                    int rb = warpM * 32 + mt * 16 + g;
                    a[mt][0] = As[rb * SA + kbase + t];
                    a[mt][1] = As[(rb + 8) * SA + kbase + t];
                    a[mt][2] = As[rb * SA + kbase + t + 4];
                    a[mt][3] = As[(rb + 8) * SA + kbase + t + 4];
                }
#pragma unroll
                for (int nt = 0; nt < 8; nt++) {
                    int col = warpN * 64 + nt * 8 + g;
                    uint32_t b0 = Bs[(kk + t) * SBW + col];
                    uint32_t b1v = Bs[(kk + t + 4) * SBW + col];
#pragma unroll
                    for (int mt = 0; mt < 2; mt++) {
                        asm volatile(
                            "mma.sync.aligned.m16n8k8.row.col.f32.tf32.tf32.f32 "
                            "{%0,%1,%2,%3}, {%4,%5,%6,%7}, {%8,%9}, {%0,%1,%2,%3};"
                            : "+f"(acc[mt][nt][0]), "+f"(acc[mt][nt][1]),
                              "+f"(acc[mt][nt][2]), "+f"(acc[mt][nt][3])
                            : "r"(a[mt][0]), "r"(a[mt][1]), "r"(a[mt][2]), "r"(a[mt][3]),
                              "r"(b0), "r"(b1v));
                    }
                }
            }
        }

        // store xt[graph][r] as fp16 (pack pairs; col stride 2 -> one u32)
        uint32_t* xt = (uint32_t*)g_xt + (size_t)(graph * RR + r) * NN * 64;
#pragma unroll
        for (int mt = 0; mt < 2; mt++) {
            int row0 = m0 + warpM * 32 + mt * 16 + g;
#pragma unroll
            for (int nt = 0; nt < 8; nt++) {
                int col2 = warpN * 32 + nt * 4 + t;   // (col pair index)
                if (row0 < NN)
                    xt[(size_t)row0 * 64 + col2] =
                        pack_f16x2(acc[mt][nt][0], acc[mt][nt][1]);
                if (row0 + 8 < NN)
                    xt[(size_t)(row0 + 8) * 64 + col2] =
                        pack_f16x2(acc[mt][nt][2], acc[mt][nt][3]);
            }
        }
    }
}

// ---------------- edge pass: denom += ex; acc[dst] += ex * xt[r,src] --------
// 16 lanes per edge: each lane loads uint4 = 8 fp16 cols, 2 red.v4 stores.
__global__ void edge_kernel(const int* __restrict__ ei1, const int* __restrict__ et1,
                            const int* __restrict__ ei2, const int* __restrict__ et2) {
    int graph = blockIdx.y;
    const int* ei = graph ? ei2 : ei1;
    const int* et = graph ? et2 : et1;
    int idx = blockIdx.x * 256 + threadIdx.x;
    int e = idx >> 4;
    if (e >= EE) return;
    int lane16 = threadIdx.x & 15;
    int src = __ldg(ei + e);
    int dst = __ldg(ei + EE + e);
    int r = __ldg(et + e);
    float al = g_qi[(graph * NN + dst) * RR + r] + g_kj[(graph * NN + src) * RR + r];
    al = al > 0.f ? al : 0.2f * al;           // leaky_relu
    float ex = __expf(al);                    // alpha ~ O(1): no max-shift
    if (lane16 == 0) atomicAdd(&g_denom[graph * NN + dst], ex);
    const uint4* xt4 = g_xt + ((size_t)(graph * RR + r) * NN + src) * 16;
    uint4 u = __ldg(&xt4[lane16]);
    float2 p0 = unpack_f16x2(u.x), p1 = unpack_f16x2(u.y);
    float2 p2 = unpack_f16x2(u.z), p3 = unpack_f16x2(u.w);
    float* p = &g_acc[((size_t)graph * NN + dst) * HD + lane16 * 8];
    asm volatile("red.global.add.v4.f32 [%0], {%1,%2,%3,%4};"
                 :: "l"(p), "f"(ex * p0.x), "f"(ex * p0.y),
                    "f"(ex * p1.x), "f"(ex * p1.y) : "memory");
    asm volatile("red.global.add.v4.f32 [%0], {%1,%2,%3,%4};"
                 :: "l"(p + 4), "f"(ex * p2.x), "f"(ex * p2.y),
                    "f"(ex * p3.x), "f"(ex * p3.y) : "memory");
}

// ---------------- out = relu(acc/denom + b) ---------------------------------
__global__ void epilogue_kernel(const float* __restrict__ b1,
                                const float* __restrict__ b2,
                                float* __restrict__ out) {
    int graph = blockIdx.y;
    const float* bias = graph ? b2 : b1;
    int i = blockIdx.x * blockDim.x + threadIdx.x;   // over NN*32 float4s
    if (i >= NN * 32) return;
    int n = i >> 5, c4 = i & 31;
    float inv = 1.0f / (g_denom[graph * NN + n] + 1e-16f);
    float4 v = ((const float4*)g_acc)[(size_t)graph * NN * 32 + i];
    float4 bb = ((const float4*)bias)[c4];
    v.x = fmaxf(v.x * inv + bb.x, 0.f);
    v.y = fmaxf(v.y * inv + bb.y, 0.f);
    v.z = fmaxf(v.z * inv + bb.z, 0.f);
    v.w = fmaxf(v.w * inv + bb.w, 0.f);
    ((float4*)out)[(size_t)graph * NN * 32 + i] = v;
}

// ---------------- driver ----------------------------------------------------
extern "C" void kernel_launch(void* const* d_in, const int* in_sizes, int n_in,
                              void* d_out, int out_size) {
    const float* x1  = (const float*)d_in[0];
    const int*   ei1 = (const int*)d_in[1];
    const int*   et1 = (const int*)d_in[2];
    const float* x2  = (const float*)d_in[3];
    const int*   ei2 = (const int*)d_in[4];
    const int*   et2 = (const int*)d_in[5];
    const float* W1  = (const float*)d_in[6];
    const float* q1  = (const float*)d_in[7];
    const float* k1  = (const float*)d_in[8];
    const float* b1  = (const float*)d_in[9];
    const float* W2  = (const float*)d_in[10];
    const float* q2  = (const float*)d_in[11];
    const float* k2  = (const float*)d_in[12];
    const float* b2  = (const float*)d_in[13];
    float* out = (float*)d_out;

    cudaFuncSetAttribute(xt_gemm, cudaFuncAttributeMaxDynamicSharedMemorySize,
                         GEMM_SMEM);

    prep_kernel<<<2048, 256>>>();
    wqwk_kernel<<<dim3((RR * HD) / 8, NG), 256>>>(W1, q1, k1, W2, q2, k2);
    table_kernel<<<dim3((NN + 7) / 8, NG), 256>>>(x1, x2);
    xt_gemm<<<dim3(MBLK, NG), 256, GEMM_SMEM>>>(x1, x2, W1, W2);
    edge_kernel<<<dim3(EE / 16, NG), 256>>>(ei1, et1, ei2, et2);
    epilogue_kernel<<<dim3((NN * 32 + 255) / 256, NG), 256>>>(b1, b2, out);
}

// round 16
// speedup vs baseline: 1.3434x; 1.1184x over previous
#include <cuda_runtime.h>
#include <cstdint>

#define NN 50000
#define EE 800000
#define RR 8
#define HD 128
#define NG 2            // graphs

#define GM 128
#define PW 68           // smem row stride in u32 (fp16 pairs): 68 % 32 == 4 -> conflict-free
#define MBLK ((NN + GM - 1) / GM)
#define GEMM_SMEM ((GM * PW + HD * PW) * 4)   // 34816 + 34816 = 69632 -> 2 CTAs/SM

// ---------------- scratch (device globals; no allocation allowed) ----------
__device__ uint4 g_xt[(size_t)NG * RR * NN * 16];  // 204.8 MB xt fp16 [g][r][n][128]
__device__ float g_acc[(size_t)NG * NN * HD];      // 51.2 MB unnormalized agg
__device__ float g_denom[NG * NN];
__device__ float g_wq[NG * RR * HD];
__device__ float g_wk[NG * RR * HD];
__device__ float g_qi[NG * NN * RR];
__device__ float g_kj[NG * NN * RR];

// pack two f32 -> f16x2 (first arg in low half = first k element)
__device__ __forceinline__ uint32_t pack_f16x2(float lo, float hi) {
    uint32_t r;
    asm("cvt.rn.f16x2.f32 %0, %1, %2;" : "=r"(r) : "f"(hi), "f"(lo));
    return r;
}
// unpack f16x2 -> two f32
__device__ __forceinline__ float2 unpack_f16x2(uint32_t u) {
    float lo, hi;
    asm("{ .reg .b16 l, h;\n\t"
        "  mov.b32 {l, h}, %2;\n\t"
        "  cvt.f32.f16 %0, l;\n\t"
        "  cvt.f32.f16 %1, h; }"
        : "=f"(lo), "=f"(hi) : "r"(u));
    return make_float2(lo, hi);
}

// ---------------- zero acc + denom -----------------------------------------
__global__ void prep_kernel() {
    int i = blockIdx.x * blockDim.x + threadIdx.x;
    int stride = gridDim.x * blockDim.x;
    float4 z = make_float4(0.f, 0.f, 0.f, 0.f);
    float4* a4 = (float4*)g_acc;
    const int na4 = NG * NN * HD / 4;
    for (int j = i; j < na4; j += stride) a4[j] = z;
    for (int j = i; j < NG * NN; j += stride) g_denom[j] = 0.f;
}

// ---------------- Wq[r] = W_r @ q, Wk[r] = W_r @ k --------------------------
__global__ void wqwk_kernel(const float* __restrict__ W1, const float* __restrict__ q1,
                            const float* __restrict__ k1,
                            const float* __restrict__ W2, const float* __restrict__ q2,
                            const float* __restrict__ k2) {
    int graph = blockIdx.y;
    const float* W = graph ? W2 : W1;
    const float* q = graph ? q2 : q1;
    const float* k = graph ? k2 : k1;
    int w = (blockIdx.x * blockDim.x + threadIdx.x) >> 5;
    int lane = threadIdx.x & 31;
    if (w >= RR * HD) return;
    const float* row = W + (size_t)w * HD;
    float sq = 0.f, sk = 0.f;
#pragma unroll
    for (int j = lane; j < HD; j += 32) {
        float wv = row[j];
        sq += wv * q[j];
        sk += wv * k[j];
    }
#pragma unroll
    for (int o = 16; o; o >>= 1) {
        sq += __shfl_xor_sync(0xffffffffu, sq, o);
        sk += __shfl_xor_sync(0xffffffffu, sk, o);
    }
    if (lane == 0) {
        g_wq[graph * RR * HD + w] = sq;
        g_wk[graph * RR * HD + w] = sk;
    }
}

// ---------------- per-node logit tables: qi[n][r], kj[n][r] -----------------
__global__ void table_kernel(const float* __restrict__ x1,
                             const float* __restrict__ x2) {
    int graph = blockIdx.y;
    const float* x = graph ? x2 : x1;
    int n = (blockIdx.x * blockDim.x + threadIdx.x) >> 5;
    if (n >= NN) return;
    int lane = threadIdx.x & 31;
    float4 xv = ((const float4*)x)[(size_t)n * 32 + lane];
    const float4* wq4 = (const float4*)(g_wq + graph * RR * HD);
    const float4* wk4 = (const float4*)(g_wk + graph * RR * HD);
#pragma unroll
    for (int r = 0; r < RR; r++) {
        float4 wq = wq4[r * 32 + lane];
        float4 wk = wk4[r * 32 + lane];
        float sq = xv.x * wq.x + xv.y * wq.y + xv.z * wq.z + xv.w * wq.w;
        float sk = xv.x * wk.x + xv.y * wk.y + xv.z * wk.z + xv.w * wk.w;
#pragma unroll
        for (int o = 16; o; o >>= 1) {
            sq += __shfl_xor_sync(0xffffffffu, sq, o);
            sk += __shfl_xor_sync(0xffffffffu, sk, o);
        }
        if (lane == 0) {
            g_qi[(graph * NN + n) * RR + r] = sq;
            g_kj[(graph * NN + n) * RR + r] = sk;
        }
    }
}

// ---------------- xt[g][r] = x @ W_r  (fp16 mma.sync m16n8k16) --------------
// A (x tile) resident fp16 in smem, loaded once. Per r: load FULL W_r^T fp16
// tile (2 syncs), 8 K-steps of m16n8k16, fp16 store of xt. 69.6KB -> 2 CTA/SM.
__global__ __launch_bounds__(256)
void xt_gemm(const float* __restrict__ x1, const float* __restrict__ x2,
             const float* __restrict__ W1, const float* __restrict__ W2) {
    extern __shared__ uint32_t sm[];
    uint32_t* As = sm;             // [128][PW]  x tile, fp16 pairs along k
    uint32_t* Bs = sm + GM * PW;   // [128 n][PW] W_r^T, fp16 pairs along k
    int graph = blockIdx.y;
    const float* x = graph ? x2 : x1;
    const float* W = graph ? W2 : W1;
    int m0 = blockIdx.x * GM;
    int tid = threadIdx.x;
    int wid = tid >> 5, lane = tid & 31;
    int warpM = wid >> 1;    // 0..3 -> 32-row slab
    int warpN = wid & 1;     // 0..1 -> 64-col slab
    int g = lane >> 2, t = lane & 3;

    // load A tile once, convert to fp16 pairs (k-contiguous)
    for (int idx = tid; idx < GM * 32; idx += 256) {
        int row = idx >> 5, c4 = idx & 31;
        int gm = m0 + row;
        float4 v = make_float4(0.f, 0.f, 0.f, 0.f);
        if (gm < NN) v = ((const float4*)x)[(size_t)gm * 32 + c4];
        uint2 u = make_uint2(pack_f16x2(v.x, v.y), pack_f16x2(v.z, v.w));
        *(uint2*)&As[row * PW + c4 * 2] = u;
    }

    for (int r = 0; r < RR; r++) {
        const float* Wr = W + (size_t)r * HD * HD;
        __syncthreads();   // Bs (prev r) fully consumed; As ready (r=0)
        // load W_r transposed: Bs[n][kp] = (W[2kp][n], W[2kp+1][n])
#pragma unroll
        for (int i = 0; i < 32; i++) {
            int idx = tid + i * 256;
            int n = idx & 127, kp = idx >> 7;
            float w0 = __ldg(&Wr[(size_t)(2 * kp) * HD + n]);
            float w1 = __ldg(&Wr[(size_t)(2 * kp + 1) * HD + n]);
            Bs[n * PW + kp] = pack_f16x2(w0, w1);
        }
        __syncthreads();

        float acc[2][8][4];
#pragma unroll
        for (int mt = 0; mt < 2; mt++)
#pragma unroll
            for (int nt = 0; nt < 8; nt++)
#pragma unroll
                for (int c = 0; c < 4; c++) acc[mt][nt][c] = 0.f;

#pragma unroll
        for (int ks = 0; ks < 8; ks++) {       // 8 K-steps of 16
            int kb = ks * 8;                   // u32 (pair) offset
            uint32_t a[2][4];
#pragma unroll
            for (int mt = 0; mt < 2; mt++) {
                int rb = warpM * 32 + mt * 16 + g;
                a[mt][0] = As[rb * PW + kb + t];
                a[mt][1] = As[(rb + 8) * PW + kb + t];
                a[mt][2] = As[rb * PW + kb + t + 4];
                a[mt][3] = As[(rb + 8) * PW + kb + t + 4];
            }
#pragma unroll
            for (int nt = 0; nt < 8; nt++) {
                int col = warpN * 64 + nt * 8 + g;
                uint32_t b0 = Bs[col * PW + kb + t];
                uint32_t b1 = Bs[col * PW + kb + t + 4];
#pragma unroll
                for (int mt = 0; mt < 2; mt++) {
                    asm volatile(
                        "mma.sync.aligned.m16n8k16.row.col.f32.f16.f16.f32 "
                        "{%0,%1,%2,%3}, {%4,%5,%6,%7}, {%8,%9}, {%0,%1,%2,%3};"
                        : "+f"(acc[mt][nt][0]), "+f"(acc[mt][nt][1]),
                          "+f"(acc[mt][nt][2]), "+f"(acc[mt][nt][3])
                        : "r"(a[mt][0]), "r"(a[mt][1]), "r"(a[mt][2]), "r"(a[mt][3]),
                          "r"(b0), "r"(b1));
                }
            }
        }

        // store xt[graph][r] as fp16 (pack pairs; col stride 2 -> one u32)
        uint32_t* xt = (uint32_t*)g_xt + (size_t)(graph * RR + r) * NN * 64;
#pragma unroll
        for (int mt = 0; mt < 2; mt++) {
            int row0 = m0 + warpM * 32 + mt * 16 + g;
#pragma unroll
            for (int nt = 0; nt < 8; nt++) {
                int col2 = warpN * 32 + nt * 4 + t;   // (col pair index)
                if (row0 < NN)
                    xt[(size_t)row0 * 64 + col2] =
                        pack_f16x2(acc[mt][nt][0], acc[mt][nt][1]);
                if (row0 + 8 < NN)
                    xt[(size_t)(row0 + 8) * 64 + col2] =
                        pack_f16x2(acc[mt][nt][2], acc[mt][nt][3]);
            }
        }
    }
}

// ---------------- edge pass: denom += ex; acc[dst] += ex * xt[r,src] --------
// 16 lanes per edge: each lane loads uint4 = 8 fp16 cols, 2 red.v4 stores.
__global__ void edge_kernel(const int* __restrict__ ei1, const int* __restrict__ et1,
                            const int* __restrict__ ei2, const int* __restrict__ et2) {
    int graph = blockIdx.y;
    const int* ei = graph ? ei2 : ei1;
    const int* et = graph ? et2 : et1;
    int idx = blockIdx.x * 256 + threadIdx.x;
    int e = idx >> 4;
    if (e >= EE) return;
    int lane16 = threadIdx.x & 15;
    int src = __ldg(ei + e);
    int dst = __ldg(ei + EE + e);
    int r = __ldg(et + e);
    float al = g_qi[(graph * NN + dst) * RR + r] + g_kj[(graph * NN + src) * RR + r];
    al = al > 0.f ? al : 0.2f * al;           // leaky_relu
    float ex = __expf(al);                    // alpha ~ O(1): no max-shift
    if (lane16 == 0) atomicAdd(&g_denom[graph * NN + dst], ex);
    const uint4* xt4 = g_xt + ((size_t)(graph * RR + r) * NN + src) * 16;
    uint4 u = __ldg(&xt4[lane16]);
    float2 p0 = unpack_f16x2(u.x), p1 = unpack_f16x2(u.y);
    float2 p2 = unpack_f16x2(u.z), p3 = unpack_f16x2(u.w);
    float* p = &g_acc[((size_t)graph * NN + dst) * HD + lane16 * 8];
    asm volatile("red.global.add.v4.f32 [%0], {%1,%2,%3,%4};"
                 :: "l"(p), "f"(ex * p0.x), "f"(ex * p0.y),
                    "f"(ex * p1.x), "f"(ex * p1.y) : "memory");
    asm volatile("red.global.add.v4.f32 [%0], {%1,%2,%3,%4};"
                 :: "l"(p + 4), "f"(ex * p2.x), "f"(ex * p2.y),
                    "f"(ex * p3.x), "f"(ex * p3.y) : "memory");
}

// ---------------- out = relu(acc/denom + b) ---------------------------------
__global__ void epilogue_kernel(const float* __restrict__ b1,
                                const float* __restrict__ b2,
                                float* __restrict__ out) {
    int graph = blockIdx.y;
    const float* bias = graph ? b2 : b1;
    int i = blockIdx.x * blockDim.x + threadIdx.x;   // over NN*32 float4s
    if (i >= NN * 32) return;
    int n = i >> 5, c4 = i & 31;
    float inv = 1.0f / (g_denom[graph * NN + n] + 1e-16f);
    float4 v = ((const float4*)g_acc)[(size_t)graph * NN * 32 + i];
    float4 bb = ((const float4*)bias)[c4];
    v.x = fmaxf(v.x * inv + bb.x, 0.f);
    v.y = fmaxf(v.y * inv + bb.y, 0.f);
    v.z = fmaxf(v.z * inv + bb.z, 0.f);
    v.w = fmaxf(v.w * inv + bb.w, 0.f);
    ((float4*)out)[(size_t)graph * NN * 32 + i] = v;
}

// ---------------- driver ----------------------------------------------------
extern "C" void kernel_launch(void* const* d_in, const int* in_sizes, int n_in,
                              void* d_out, int out_size) {
    const float* x1  = (const float*)d_in[0];
    const int*   ei1 = (const int*)d_in[1];
    const int*   et1 = (const int*)d_in[2];
    const float* x2  = (const float*)d_in[3];
    const int*   ei2 = (const int*)d_in[4];
    const int*   et2 = (const int*)d_in[5];
    const float* W1  = (const float*)d_in[6];
    const float* q1  = (const float*)d_in[7];
    const float* k1  = (const float*)d_in[8];
    const float* b1  = (const float*)d_in[9];
    const float* W2  = (const float*)d_in[10];
    const float* q2  = (const float*)d_in[11];
    const float* k2  = (const float*)d_in[12];
    const float* b2  = (const float*)d_in[13];
    float* out = (float*)d_out;

    cudaFuncSetAttribute(xt_gemm, cudaFuncAttributeMaxDynamicSharedMemorySize,
                         GEMM_SMEM);

    prep_kernel<<<2048, 256>>>();
    wqwk_kernel<<<dim3((RR * HD) / 8, NG), 256>>>(W1, q1, k1, W2, q2, k2);
    table_kernel<<<dim3((NN + 7) / 8, NG), 256>>>(x1, x2);
    xt_gemm<<<dim3(MBLK, NG), 256, GEMM_SMEM>>>(x1, x2, W1, W2);
    edge_kernel<<<dim3(EE / 16, NG), 256>>>(ei1, et1, ei2, et2);
    epilogue_kernel<<<dim3((NN * 32 + 255) / 256, NG), 256>>>(b1, b2, out);
}